// round 1
// baseline (speedup 1.0000x reference)
#include <cuda_runtime.h>

#define BB 16
#define SS 4096
#define VV 1024
#define INV_SQRT_S 0.015625f   // 1/sqrt(4096)

// Scratch (no allocations allowed)
__device__ float g_q[BB * VV];
__device__ float g_u[BB * VV];
__device__ float g_c[BB];
__device__ float g_y[BB * VV];
__device__ float g_A[BB];

// ---------------------------------------------------------------------------
// Zero accumulators
// ---------------------------------------------------------------------------
__global__ void zero_kernel() {
    int i = blockIdx.x * blockDim.x + threadIdx.x;
    if (i < BB * VV) { g_y[i] = 0.f; g_u[i] = 0.f; }
    if (i < BB) g_A[i] = 0.f;
}

// ---------------------------------------------------------------------------
// q[b][o] = sum_v Wq[o][v] * pool[b][v] + bq[o]
// One warp per o, computes all 16 batches; pool staged in smem in 256-col chunks
// ---------------------------------------------------------------------------
__global__ void __launch_bounds__(256) q_kernel(const float* __restrict__ pool,
                                                const float* __restrict__ Wq,
                                                const float* __restrict__ bq) {
    const int warp = threadIdx.x >> 5, lane = threadIdx.x & 31;
    const int o = blockIdx.x * 8 + warp;
    __shared__ float ps[16 * 256];
    float acc[16];
#pragma unroll
    for (int b = 0; b < 16; b++) acc[b] = 0.f;

    for (int ch = 0; ch < 4; ch++) {
        __syncthreads();
        for (int i = threadIdx.x; i < 4096; i += 256) {
            int b = i >> 8, v = i & 255;
            ps[i] = pool[b * VV + ch * 256 + v];
        }
        __syncthreads();
#pragma unroll
        for (int j = 0; j < 8; j++) {
            float w = Wq[o * VV + ch * 256 + j * 32 + lane];
#pragma unroll
            for (int b = 0; b < 16; b++)
                acc[b] += w * ps[b * 256 + j * 32 + lane];
        }
    }
#pragma unroll
    for (int b = 0; b < 16; b++) {
        float r = acc[b];
#pragma unroll
        for (int off = 16; off; off >>= 1) r += __shfl_xor_sync(0xffffffffu, r, off);
        if (lane == 0) g_q[b * VV + o] = r + bq[o];
    }
}

// ---------------------------------------------------------------------------
// u[b][v] = sum_o q[b][o] * Wk[o][v]   (coalesced along v; o split for parallelism)
// ---------------------------------------------------------------------------
__global__ void __launch_bounds__(256) u_kernel(const float* __restrict__ Wk) {
    __shared__ float qs[16 * 32];
    const int v = blockIdx.x * 256 + threadIdx.x;
    const int o0 = blockIdx.y * 32;
    for (int i = threadIdx.x; i < 512; i += 256) {
        int b = i >> 5, oo = i & 31;
        qs[i] = g_q[b * VV + o0 + oo];
    }
    __syncthreads();
    float acc[16];
#pragma unroll
    for (int b = 0; b < 16; b++) acc[b] = 0.f;
    for (int oo = 0; oo < 32; oo++) {
        float w = Wk[(o0 + oo) * VV + v];
#pragma unroll
        for (int b = 0; b < 16; b++) acc[b] += qs[b * 32 + oo] * w;
    }
#pragma unroll
    for (int b = 0; b < 16; b++) atomicAdd(&g_u[b * VV + v], acc[b]);
}

// ---------------------------------------------------------------------------
// c[b] = dot(q[b], bk)
// ---------------------------------------------------------------------------
__global__ void c_kernel(const float* __restrict__ bk) {
    const int warp = threadIdx.x >> 5, lane = threadIdx.x & 31;
    if (warp < BB) {
        float s = 0.f;
#pragma unroll
        for (int j = 0; j < 32; j++)
            s += g_q[warp * VV + j * 32 + lane] * bk[j * 32 + lane];
#pragma unroll
        for (int off = 16; off; off >>= 1) s += __shfl_xor_sync(0xffffffffu, s, off);
        if (lane == 0) g_c[warp] = s;
    }
}

// ---------------------------------------------------------------------------
// Fused main pass over bert_output (single read of 268 MB):
//   a = (u_b . x + c_b)/sqrt(S);  y_b += a*x;  A_b += a
// One warp per 16 rows; lane holds 32 columns as 8 float4.
// ---------------------------------------------------------------------------
__global__ void __launch_bounds__(256) main_kernel(const float* __restrict__ X) {
    const int b = blockIdx.y;
    const int warp = threadIdx.x >> 5, lane = threadIdx.x & 31;

    float4 u4[8];
    const float4* ub = reinterpret_cast<const float4*>(g_u + b * VV);
#pragma unroll
    for (int j = 0; j < 8; j++) u4[j] = ub[j * 32 + lane];
    const float cb = g_c[b];

    float yacc[32];
#pragma unroll
    for (int i = 0; i < 32; i++) yacc[i] = 0.f;
    float Aacc = 0.f;

    const int row0 = (blockIdx.x * 8 + warp) * 16;
    const float4* Xb = reinterpret_cast<const float4*>(X + (size_t)b * SS * VV);

    for (int r = 0; r < 16; r++) {
        const float4* xr = Xb + (size_t)(row0 + r) * (VV / 4);
        float4 x4[8];
#pragma unroll
        for (int j = 0; j < 8; j++) x4[j] = xr[j * 32 + lane];

        float d = 0.f;
#pragma unroll
        for (int j = 0; j < 8; j++)
            d += x4[j].x * u4[j].x + x4[j].y * u4[j].y +
                 x4[j].z * u4[j].z + x4[j].w * u4[j].w;
#pragma unroll
        for (int off = 16; off; off >>= 1) d += __shfl_xor_sync(0xffffffffu, d, off);

        const float a = (d + cb) * INV_SQRT_S;
        Aacc += a;
#pragma unroll
        for (int j = 0; j < 8; j++) {
            yacc[j * 4 + 0] += a * x4[j].x;
            yacc[j * 4 + 1] += a * x4[j].y;
            yacc[j * 4 + 2] += a * x4[j].z;
            yacc[j * 4 + 3] += a * x4[j].w;
        }
    }

    __shared__ float ys[VV];
    __shared__ float As;
    for (int i = threadIdx.x; i < VV; i += 256) ys[i] = 0.f;
    if (threadIdx.x == 0) As = 0.f;
    __syncthreads();
#pragma unroll
    for (int j = 0; j < 8; j++) {
        int col = j * 128 + lane * 4;
        atomicAdd(&ys[col + 0], yacc[j * 4 + 0]);
        atomicAdd(&ys[col + 1], yacc[j * 4 + 1]);
        atomicAdd(&ys[col + 2], yacc[j * 4 + 2]);
        atomicAdd(&ys[col + 3], yacc[j * 4 + 3]);
    }
    if (lane == 0) atomicAdd(&As, Aacc);
    __syncthreads();
    for (int i = threadIdx.x; i < VV; i += 256) atomicAdd(&g_y[b * VV + i], ys[i]);
    if (threadIdx.x == 0) atomicAdd(&g_A[b], As);
}

// ---------------------------------------------------------------------------
// out[b][o] = sum_v Wv[o][v] * y[b][v] + A[b]*bv[o]
// One warp per o, all 16 batches; y staged in smem in 256-col chunks
// ---------------------------------------------------------------------------
__global__ void __launch_bounds__(256) epilogue_kernel(const float* __restrict__ Wv,
                                                       const float* __restrict__ bv,
                                                       float* __restrict__ out) {
    const int warp = threadIdx.x >> 5, lane = threadIdx.x & 31;
    const int o = blockIdx.x * 8 + warp;
    __shared__ float ysm[16 * 256];
    float acc[16];
#pragma unroll
    for (int b = 0; b < 16; b++) acc[b] = 0.f;

    for (int ch = 0; ch < 4; ch++) {
        __syncthreads();
        for (int i = threadIdx.x; i < 4096; i += 256) {
            int b = i >> 8, v = i & 255;
            ysm[i] = g_y[b * VV + ch * 256 + v];
        }
        __syncthreads();
#pragma unroll
        for (int j = 0; j < 8; j++) {
            float w = Wv[o * VV + ch * 256 + j * 32 + lane];
#pragma unroll
            for (int b = 0; b < 16; b++)
                acc[b] += w * ysm[b * 256 + j * 32 + lane];
        }
    }
#pragma unroll
    for (int b = 0; b < 16; b++) {
        float r = acc[b];
#pragma unroll
        for (int off = 16; off; off >>= 1) r += __shfl_xor_sync(0xffffffffu, r, off);
        if (lane == 0) out[b * VV + o] = r + g_A[b] * bv[o];
    }
}

// ---------------------------------------------------------------------------
extern "C" void kernel_launch(void* const* d_in, const int* in_sizes, int n_in,
                              void* d_out, int out_size) {
    const float* pool = (const float*)d_in[0];
    const float* bert = (const float*)d_in[1];
    const float* Wq   = (const float*)d_in[2];
    const float* bq   = (const float*)d_in[3];
    const float* Wk   = (const float*)d_in[4];
    const float* bk   = (const float*)d_in[5];
    const float* Wv   = (const float*)d_in[6];
    const float* bv   = (const float*)d_in[7];
    float* out = (float*)d_out;

    zero_kernel<<<64, 256>>>();
    q_kernel<<<128, 256>>>(pool, Wq, bq);
    dim3 ug(4, 32);
    u_kernel<<<ug, 256>>>(Wk);
    c_kernel<<<1, 512>>>(bk);
    dim3 mg(32, 16);
    main_kernel<<<mg, 256>>>(bert);
    epilogue_kernel<<<128, 256>>>(Wv, bv, out);
}

// round 2
// speedup vs baseline: 1.0025x; 1.0025x over previous
#include <cuda_runtime.h>

#define BB 16
#define SS 4096
#define VV 1024
#define INV_SQRT_S 0.015625f   // 1/sqrt(4096)

// Scratch (no allocations allowed)
__device__ float g_q[BB * VV];
__device__ float g_u[BB * VV];
__device__ float g_c[BB];
__device__ float g_y[BB * VV];
__device__ float g_A[BB];

// ---------------------------------------------------------------------------
// Zero accumulators
// ---------------------------------------------------------------------------
__global__ void zero_kernel() {
    int i = blockIdx.x * blockDim.x + threadIdx.x;
    if (i < BB * VV) { g_y[i] = 0.f; g_u[i] = 0.f; }
    if (i < BB) g_A[i] = 0.f;
}

// ---------------------------------------------------------------------------
// q[b][o] = sum_v Wq[o][v] * pool[b][v] + bq[o]
// One warp per o, computes all 16 batches; pool staged in smem in 256-col chunks
// ---------------------------------------------------------------------------
__global__ void __launch_bounds__(256) q_kernel(const float* __restrict__ pool,
                                                const float* __restrict__ Wq,
                                                const float* __restrict__ bq) {
    const int warp = threadIdx.x >> 5, lane = threadIdx.x & 31;
    const int o = blockIdx.x * 8 + warp;
    __shared__ float ps[16 * 256];
    float acc[16];
#pragma unroll
    for (int b = 0; b < 16; b++) acc[b] = 0.f;

    for (int ch = 0; ch < 4; ch++) {
        __syncthreads();
        for (int i = threadIdx.x; i < 4096; i += 256) {
            int b = i >> 8, v = i & 255;
            ps[i] = pool[b * VV + ch * 256 + v];
        }
        __syncthreads();
#pragma unroll
        for (int j = 0; j < 8; j++) {
            float w = Wq[o * VV + ch * 256 + j * 32 + lane];
#pragma unroll
            for (int b = 0; b < 16; b++)
                acc[b] += w * ps[b * 256 + j * 32 + lane];
        }
    }
#pragma unroll
    for (int b = 0; b < 16; b++) {
        float r = acc[b];
#pragma unroll
        for (int off = 16; off; off >>= 1) r += __shfl_xor_sync(0xffffffffu, r, off);
        if (lane == 0) g_q[b * VV + o] = r + bq[o];
    }
}

// ---------------------------------------------------------------------------
// u[b][v] = sum_o q[b][o] * Wk[o][v]   (coalesced along v; o split for parallelism)
// ---------------------------------------------------------------------------
__global__ void __launch_bounds__(256) u_kernel(const float* __restrict__ Wk) {
    __shared__ float qs[16 * 32];
    const int v = blockIdx.x * 256 + threadIdx.x;
    const int o0 = blockIdx.y * 32;
    for (int i = threadIdx.x; i < 512; i += 256) {
        int b = i >> 5, oo = i & 31;
        qs[i] = g_q[b * VV + o0 + oo];
    }
    __syncthreads();
    float acc[16];
#pragma unroll
    for (int b = 0; b < 16; b++) acc[b] = 0.f;
    for (int oo = 0; oo < 32; oo++) {
        float w = Wk[(o0 + oo) * VV + v];
#pragma unroll
        for (int b = 0; b < 16; b++) acc[b] += qs[b * 32 + oo] * w;
    }
#pragma unroll
    for (int b = 0; b < 16; b++) atomicAdd(&g_u[b * VV + v], acc[b]);
}

// ---------------------------------------------------------------------------
// c[b] = dot(q[b], bk)
// ---------------------------------------------------------------------------
__global__ void c_kernel(const float* __restrict__ bk) {
    const int warp = threadIdx.x >> 5, lane = threadIdx.x & 31;
    if (warp < BB) {
        float s = 0.f;
#pragma unroll
        for (int j = 0; j < 32; j++)
            s += g_q[warp * VV + j * 32 + lane] * bk[j * 32 + lane];
#pragma unroll
        for (int off = 16; off; off >>= 1) s += __shfl_xor_sync(0xffffffffu, s, off);
        if (lane == 0) g_c[warp] = s;
    }
}

// ---------------------------------------------------------------------------
// Fused main pass over bert_output (single read of 268 MB):
//   a = (u_b . x + c_b)/sqrt(S);  y_b += a*x;  A_b += a
// One warp per 16 rows; lane holds 32 columns as 8 float4.
// ---------------------------------------------------------------------------
__global__ void __launch_bounds__(256) main_kernel(const float* __restrict__ X) {
    const int b = blockIdx.y;
    const int warp = threadIdx.x >> 5, lane = threadIdx.x & 31;

    float4 u4[8];
    const float4* ub = reinterpret_cast<const float4*>(g_u + b * VV);
#pragma unroll
    for (int j = 0; j < 8; j++) u4[j] = ub[j * 32 + lane];
    const float cb = g_c[b];

    float yacc[32];
#pragma unroll
    for (int i = 0; i < 32; i++) yacc[i] = 0.f;
    float Aacc = 0.f;

    const int row0 = (blockIdx.x * 8 + warp) * 16;
    const float4* Xb = reinterpret_cast<const float4*>(X + (size_t)b * SS * VV);

    for (int r = 0; r < 16; r++) {
        const float4* xr = Xb + (size_t)(row0 + r) * (VV / 4);
        float4 x4[8];
#pragma unroll
        for (int j = 0; j < 8; j++) x4[j] = xr[j * 32 + lane];

        float d = 0.f;
#pragma unroll
        for (int j = 0; j < 8; j++)
            d += x4[j].x * u4[j].x + x4[j].y * u4[j].y +
                 x4[j].z * u4[j].z + x4[j].w * u4[j].w;
#pragma unroll
        for (int off = 16; off; off >>= 1) d += __shfl_xor_sync(0xffffffffu, d, off);

        const float a = (d + cb) * INV_SQRT_S;
        Aacc += a;
#pragma unroll
        for (int j = 0; j < 8; j++) {
            yacc[j * 4 + 0] += a * x4[j].x;
            yacc[j * 4 + 1] += a * x4[j].y;
            yacc[j * 4 + 2] += a * x4[j].z;
            yacc[j * 4 + 3] += a * x4[j].w;
        }
    }

    __shared__ float ys[VV];
    __shared__ float As;
    for (int i = threadIdx.x; i < VV; i += 256) ys[i] = 0.f;
    if (threadIdx.x == 0) As = 0.f;
    __syncthreads();
#pragma unroll
    for (int j = 0; j < 8; j++) {
        int col = j * 128 + lane * 4;
        atomicAdd(&ys[col + 0], yacc[j * 4 + 0]);
        atomicAdd(&ys[col + 1], yacc[j * 4 + 1]);
        atomicAdd(&ys[col + 2], yacc[j * 4 + 2]);
        atomicAdd(&ys[col + 3], yacc[j * 4 + 3]);
    }
    if (lane == 0) atomicAdd(&As, Aacc);
    __syncthreads();
    for (int i = threadIdx.x; i < VV; i += 256) atomicAdd(&g_y[b * VV + i], ys[i]);
    if (threadIdx.x == 0) atomicAdd(&g_A[b], As);
}

// ---------------------------------------------------------------------------
// out[b][o] = sum_v Wv[o][v] * y[b][v] + A[b]*bv[o]
// One warp per o, all 16 batches; y staged in smem in 256-col chunks
// ---------------------------------------------------------------------------
__global__ void __launch_bounds__(256) epilogue_kernel(const float* __restrict__ Wv,
                                                       const float* __restrict__ bv,
                                                       float* __restrict__ out) {
    const int warp = threadIdx.x >> 5, lane = threadIdx.x & 31;
    const int o = blockIdx.x * 8 + warp;
    __shared__ float ysm[16 * 256];
    float acc[16];
#pragma unroll
    for (int b = 0; b < 16; b++) acc[b] = 0.f;

    for (int ch = 0; ch < 4; ch++) {
        __syncthreads();
        for (int i = threadIdx.x; i < 4096; i += 256) {
            int b = i >> 8, v = i & 255;
            ysm[i] = g_y[b * VV + ch * 256 + v];
        }
        __syncthreads();
#pragma unroll
        for (int j = 0; j < 8; j++) {
            float w = Wv[o * VV + ch * 256 + j * 32 + lane];
#pragma unroll
            for (int b = 0; b < 16; b++)
                acc[b] += w * ysm[b * 256 + j * 32 + lane];
        }
    }
#pragma unroll
    for (int b = 0; b < 16; b++) {
        float r = acc[b];
#pragma unroll
        for (int off = 16; off; off >>= 1) r += __shfl_xor_sync(0xffffffffu, r, off);
        if (lane == 0) out[b * VV + o] = r + g_A[b] * bv[o];
    }
}

// ---------------------------------------------------------------------------
extern "C" void kernel_launch(void* const* d_in, const int* in_sizes, int n_in,
                              void* d_out, int out_size) {
    const float* pool = (const float*)d_in[0];
    const float* bert = (const float*)d_in[1];
    const float* Wq   = (const float*)d_in[2];
    const float* bq   = (const float*)d_in[3];
    const float* Wk   = (const float*)d_in[4];
    const float* bk   = (const float*)d_in[5];
    const float* Wv   = (const float*)d_in[6];
    const float* bv   = (const float*)d_in[7];
    float* out = (float*)d_out;

    zero_kernel<<<64, 256>>>();
    q_kernel<<<128, 256>>>(pool, Wq, bq);
    dim3 ug(4, 32);
    u_kernel<<<ug, 256>>>(Wk);
    c_kernel<<<1, 512>>>(bk);
    dim3 mg(32, 16);
    main_kernel<<<mg, 256>>>(bert);
    epilogue_kernel<<<128, 256>>>(Wv, bv, out);
}